// round 2
// baseline (speedup 1.0000x reference)
#include <cuda_runtime.h>
#include <math.h>

#define NQ 10
#define DIMQ 1024
#define NL 2
#define NTHREADS 256

__global__ __launch_bounds__(NTHREADS)
void qsim_kernel(const float* __restrict__ x,
                 const float* __restrict__ w,
                 float* __restrict__ out)
{
    __shared__ float s_re[DIMQ];
    __shared__ float s_im[DIMQ];
    __shared__ float2 g[NL * NQ][4];   // u00,u01,u10,u11 per gate
    __shared__ float red[8];
    __shared__ float zacc[NQ];

    const int b = blockIdx.x;
    const int t = threadIdx.x;

    // ---- Precompute the 20 Rot gate matrices (once per block) ----
    if (t < NL * NQ) {
        float phi = w[t * 3 + 0];
        float th  = w[t * 3 + 1];
        float om  = w[t * 3 + 2];
        float ch = cosf(th * 0.5f);
        float sh = sinf(th * 0.5f);
        float ap = 0.5f * (phi + om);
        float am = 0.5f * (phi - om);
        float ca, sa, cb, sb;
        sincosf(ap, &sa, &ca);
        sincosf(am, &sb, &cb);
        // u00 = e^{-i ap} ch ; u01 = -e^{+i am} sh ; u10 = e^{-i am} sh ; u11 = e^{+i ap} ch
        g[t][0] = make_float2( ca * ch, -sa * ch);
        g[t][1] = make_float2(-cb * sh, -sb * sh);
        g[t][2] = make_float2( cb * sh, -sb * sh);
        g[t][3] = make_float2( ca * ch,  sa * ch);
    }
    if (t < NQ) zacc[t] = 0.0f;

    // ---- Load + normalize (AmplitudeEmbedding) ----
    const float* xb = x + (size_t)b * DIMQ;
    float v[4];
    float ss = 0.0f;
#pragma unroll
    for (int j = 0; j < 4; j++) {
        v[j] = xb[t + j * NTHREADS];
        ss += v[j] * v[j];
    }
#pragma unroll
    for (int o = 16; o > 0; o >>= 1)
        ss += __shfl_xor_sync(0xffffffffu, ss, o);
    if ((t & 31) == 0) red[t >> 5] = ss;
    __syncthreads();
    float tot = red[0] + red[1] + red[2] + red[3] + red[4] + red[5] + red[6] + red[7];
    float inv = rsqrtf(tot);
#pragma unroll
    for (int j = 0; j < 4; j++) {
        s_re[t + j * NTHREADS] = v[j] * inv;
        s_im[t + j * NTHREADS] = 0.0f;
    }
    __syncthreads();

    // ---- Circuit: per layer, Rot on each wire, then CNOT ring ----
#pragma unroll
    for (int l = 0; l < NL; l++) {
#pragma unroll
        for (int q = 0; q < NQ; q++) {
            const int bbit = (NQ - 1) - q;          // wire 0 = most significant bit
            const int mask = 1 << bbit;
            const int gi = l * NQ + q;
            const float2 u00 = g[gi][0], u01 = g[gi][1], u10 = g[gi][2], u11 = g[gi][3];
#pragma unroll
            for (int j = 0; j < 2; j++) {
                int p  = t + j * NTHREADS;          // 512 pairs
                int i0 = ((p >> bbit) << (bbit + 1)) | (p & (mask - 1));
                int i1 = i0 | mask;
                float ar = s_re[i0], ai = s_im[i0];
                float br = s_re[i1], bi = s_im[i1];
                float nr0 = u00.x * ar - u00.y * ai + u01.x * br - u01.y * bi;
                float ni0 = u00.x * ai + u00.y * ar + u01.x * bi + u01.y * br;
                float nr1 = u10.x * ar - u10.y * ai + u11.x * br - u11.y * bi;
                float ni1 = u10.x * ai + u10.y * ar + u11.x * bi + u11.y * br;
                s_re[i0] = nr0; s_im[i0] = ni0;
                s_re[i1] = nr1; s_im[i1] = ni1;
            }
            __syncthreads();
        }
        const int r = (l % (NQ - 1)) + 1;           // PennyLane default range
#pragma unroll
        for (int q = 0; q < NQ; q++) {
            const int cbit = (NQ - 1) - q;
            const int tbit = (NQ - 1) - ((q + r) % NQ);
            const int blo = cbit < tbit ? cbit : tbit;
            const int bhi = cbit < tbit ? tbit : cbit;
            // 256 pairs: insert zeros at blo/bhi into 8-bit index, set control=1
            int p   = t;
            int tmp = ((p >> blo) << (blo + 1)) | (p & ((1 << blo) - 1));
            int i0  = ((tmp >> bhi) << (bhi + 1)) | (tmp & ((1 << bhi) - 1));
            i0 |= (1 << cbit);                      // control = 1, target = 0
            int i1 = i0 | (1 << tbit);              // control = 1, target = 1
            float tr = s_re[i0]; s_re[i0] = s_re[i1]; s_re[i1] = tr;
            float ti = s_im[i0]; s_im[i0] = s_im[i1]; s_im[i1] = ti;
            __syncthreads();
        }
    }

    // ---- probs -> PauliZ expvals ----
    float acc[NQ];
#pragma unroll
    for (int i = 0; i < NQ; i++) acc[i] = 0.0f;
#pragma unroll
    for (int j = 0; j < 4; j++) {
        int k = t + j * NTHREADS;
        float pr = s_re[k] * s_re[k] + s_im[k] * s_im[k];
#pragma unroll
        for (int i = 0; i < NQ; i++)
            acc[i] += ((k >> ((NQ - 1) - i)) & 1) ? -pr : pr;
    }
#pragma unroll
    for (int o = 16; o > 0; o >>= 1) {
#pragma unroll
        for (int i = 0; i < NQ; i++)
            acc[i] += __shfl_xor_sync(0xffffffffu, acc[i], o);
    }
    if ((t & 31) == 0) {
#pragma unroll
        for (int i = 0; i < NQ; i++)
            atomicAdd(&zacc[i], acc[i]);
    }
    __syncthreads();
    if (t < NQ) out[(size_t)b * NQ + t] = zacc[t];
}

extern "C" void kernel_launch(void* const* d_in, const int* in_sizes, int n_in,
                              void* d_out, int out_size)
{
    // metadata order: x [16384,1024] f32, weights [2,10,3] f32. Be robust to swap.
    const float* x;
    const float* w;
    if (in_sizes[0] == NL * NQ * 3) {
        w = (const float*)d_in[0];
        x = (const float*)d_in[1];
    } else {
        x = (const float*)d_in[0];
        w = (const float*)d_in[1];
    }
    int xsize = (in_sizes[0] == NL * NQ * 3) ? in_sizes[1] : in_sizes[0];
    int B = xsize / DIMQ;
    float* out = (float*)d_out;
    qsim_kernel<<<B, NTHREADS>>>(x, w, out);
    (void)n_in; (void)out_size;
}

// round 3
// speedup vs baseline: 3.0671x; 3.0671x over previous
#include <cuda_runtime.h>
#include <math.h>

#define NQ 10
#define DIMQ 1024
#define NL 2
#define WPB 8
#define NTHREADS (WPB * 32)

// Precomputed 2x2 gate matrices: [gate][0]=(u00r,u00i,u01r,u01i), [1]=(u10r,u10i,u11r,u11i)
__device__ float4 g_gates[NL * NQ][2];

__global__ void gate_prep_kernel(const float* __restrict__ w)
{
    int t = threadIdx.x;
    if (t < NL * NQ) {
        float phi = w[t * 3 + 0];
        float th  = w[t * 3 + 1];
        float om  = w[t * 3 + 2];
        float ch = cosf(th * 0.5f);
        float sh = sinf(th * 0.5f);
        float ap = 0.5f * (phi + om);
        float am = 0.5f * (phi - om);
        float ca, sa, cb, sb;
        sincosf(ap, &sa, &ca);
        sincosf(am, &sb, &cb);
        // u00 = e^{-i ap} ch ; u01 = -e^{+i am} sh ; u10 = e^{-i am} sh ; u11 = e^{+i ap} ch
        g_gates[t][0] = make_float4( ca * ch, -sa * ch, -cb * sh, -sb * sh);
        g_gates[t][1] = make_float4( cb * sh, -sb * sh,  ca * ch,  sa * ch);
    }
}

__global__ __launch_bounds__(NTHREADS, 2)
void qsim_reg_kernel(const float* __restrict__ x, float* __restrict__ out, int B)
{
    const int lane = threadIdx.x & 31;
    const int warp = threadIdx.x >> 5;
    const int b = blockIdx.x * WPB + warp;
    if (b >= B) return;

    // State: amplitude index k = lane*32 + r  (bit 9..5 = lane, bit 4..0 = r)
    float re[32], im[32];

    // ---- Load + normalize ----
    const float4* xb = (const float4*)(x + (size_t)b * DIMQ + lane * 32);
    float ss = 0.0f;
#pragma unroll
    for (int j = 0; j < 8; j++) {
        float4 v = xb[j];
        re[4 * j + 0] = v.x; re[4 * j + 1] = v.y;
        re[4 * j + 2] = v.z; re[4 * j + 3] = v.w;
        ss += v.x * v.x + v.y * v.y + v.z * v.z + v.w * v.w;
    }
#pragma unroll
    for (int o = 16; o > 0; o >>= 1)
        ss += __shfl_xor_sync(0xffffffffu, ss, o);
    const float inv = rsqrtf(ss);
#pragma unroll
    for (int r = 0; r < 32; r++) { re[r] *= inv; im[r] = 0.0f; }

    // ---- Circuit ----
#pragma unroll
    for (int l = 0; l < NL; l++) {
        // Rot on every wire
#pragma unroll
        for (int q = 0; q < NQ; q++) {
            const int gi = l * NQ + q;
            const float4 ga = __ldg(&g_gates[gi][0]); // u00, u01
            const float4 gb = __ldg(&g_gates[gi][1]); // u10, u11
            const int bit = 9 - q;
            if (bit >= 5) {
                // lane-bit gate: exchange partner amp via shuffle
                const int m = 1 << (bit - 5);
                const bool bv = (lane >> (bit - 5)) & 1;
                // own-row coefficient ca, other-amp coefficient cb:
                //   bv==0: new = u00*own + u01*other
                //   bv==1: new = u11*own + u10*other
                const float car = bv ? gb.z : ga.x;
                const float cai = bv ? gb.w : ga.y;
                const float cbr = bv ? gb.x : ga.z;
                const float cbi = bv ? gb.y : ga.w;
#pragma unroll
                for (int r = 0; r < 32; r++) {
                    float o_re = __shfl_xor_sync(0xffffffffu, re[r], m);
                    float o_im = __shfl_xor_sync(0xffffffffu, im[r], m);
                    float sr = re[r], si = im[r];
                    re[r] = car * sr - cai * si + cbr * o_re - cbi * o_im;
                    im[r] = car * si + cai * sr + cbr * o_im + cbi * o_re;
                }
            } else {
                // register-bit gate: compile-time register pairs
                const int m = 1 << bit;
#pragma unroll
                for (int r0 = 0; r0 < 32; r0++) {
                    if (((r0 >> bit) & 1) == 0) {
                        const int r1 = r0 | m;
                        float ar = re[r0], ai = im[r0];
                        float br = re[r1], bi = im[r1];
                        re[r0] = ga.x * ar - ga.y * ai + ga.z * br - ga.w * bi;
                        im[r0] = ga.x * ai + ga.y * ar + ga.z * bi + ga.w * br;
                        re[r1] = gb.x * ar - gb.y * ai + gb.z * br - gb.w * bi;
                        im[r1] = gb.x * ai + gb.y * ar + gb.z * bi + gb.w * br;
                    }
                }
            }
        }
        // CNOT ring, range (l % 9) + 1
        const int roff = (l % (NQ - 1)) + 1;
#pragma unroll
        for (int q = 0; q < NQ; q++) {
            const int cbit = 9 - q;
            const int tbit = 9 - ((q + roff) % NQ);
            if (cbit < 5 && tbit < 5) {
                // both register bits: static swaps (free via renaming)
#pragma unroll
                for (int r = 0; r < 32; r++) {
                    if (((r >> cbit) & 1) == 1 && ((r >> tbit) & 1) == 0) {
                        const int r2 = r | (1 << tbit);
                        float t1 = re[r]; re[r] = re[r2]; re[r2] = t1;
                        float t2 = im[r]; im[r] = im[r2]; im[r2] = t2;
                    }
                }
            } else if (cbit < 5 && tbit >= 5) {
                // control in registers, target across lanes: shuffle-swap
                const int tm = 1 << (tbit - 5);
#pragma unroll
                for (int r = 0; r < 32; r++) {
                    if ((r >> cbit) & 1) {
                        re[r] = __shfl_xor_sync(0xffffffffu, re[r], tm);
                        im[r] = __shfl_xor_sync(0xffffffffu, im[r], tm);
                    }
                }
            } else if (cbit >= 5 && tbit < 5) {
                // control on lanes, target in registers: predicated register swap
                const bool cs = (lane >> (cbit - 5)) & 1;
#pragma unroll
                for (int r = 0; r < 32; r++) {
                    if (((r >> tbit) & 1) == 0) {
                        const int r2 = r | (1 << tbit);
                        float nr  = cs ? re[r2] : re[r];
                        float nr2 = cs ? re[r]  : re[r2];
                        float ni  = cs ? im[r2] : im[r];
                        float ni2 = cs ? im[r]  : im[r2];
                        re[r] = nr; re[r2] = nr2;
                        im[r] = ni; im[r2] = ni2;
                    }
                }
            } else {
                // both lane bits: shuffle + select
                const bool cs = (lane >> (cbit - 5)) & 1;
                const int tm = 1 << (tbit - 5);
#pragma unroll
                for (int r = 0; r < 32; r++) {
                    float o_re = __shfl_xor_sync(0xffffffffu, re[r], tm);
                    float o_im = __shfl_xor_sync(0xffffffffu, im[r], tm);
                    re[r] = cs ? o_re : re[r];
                    im[r] = cs ? o_im : im[r];
                }
            }
        }
    }

    // ---- probs -> PauliZ expvals ----
    float tot = 0.0f;
    float accreg[5];
#pragma unroll
    for (int i = 0; i < 5; i++) accreg[i] = 0.0f;
#pragma unroll
    for (int r = 0; r < 32; r++) {
        float pr = re[r] * re[r] + im[r] * im[r];
        tot += pr;
#pragma unroll
        for (int i = 0; i < 5; i++) {
            // wire 5+i -> bit (4-i) of r
            if ((r >> (4 - i)) & 1) accreg[i] -= pr; else accreg[i] += pr;
        }
    }
    float acc[10];
#pragma unroll
    for (int i = 0; i < 5; i++) {
        // wire i -> lane bit (4-i)
        acc[i] = ((lane >> (4 - i)) & 1) ? -tot : tot;
        acc[5 + i] = accreg[i];
    }
#pragma unroll
    for (int o = 16; o > 0; o >>= 1) {
#pragma unroll
        for (int i = 0; i < 10; i++)
            acc[i] += __shfl_xor_sync(0xffffffffu, acc[i], o);
    }
#pragma unroll
    for (int i = 0; i < 10; i++)
        if (lane == i) out[(size_t)b * NQ + i] = acc[i];
}

extern "C" void kernel_launch(void* const* d_in, const int* in_sizes, int n_in,
                              void* d_out, int out_size)
{
    const float* x;
    const float* w;
    int xsize;
    if (in_sizes[0] == NL * NQ * 3) {
        w = (const float*)d_in[0];
        x = (const float*)d_in[1];
        xsize = in_sizes[1];
    } else {
        x = (const float*)d_in[0];
        w = (const float*)d_in[1];
        xsize = in_sizes[0];
    }
    const int B = xsize / DIMQ;
    float* out = (float*)d_out;
    gate_prep_kernel<<<1, 32>>>(w);
    qsim_reg_kernel<<<(B + WPB - 1) / WPB, NTHREADS>>>(x, out, B);
    (void)n_in; (void)out_size;
}

// round 4
// speedup vs baseline: 3.4749x; 1.1330x over previous
#include <cuda_runtime.h>
#include <math.h>

#define NQ 10
#define DIMQ 1024
#define NL 2
#define WPB 8
#define NTHREADS (WPB * 32)

// Precomputed 2x2 gate matrices: [gate][0]=(u00r,u00i,u01r,u01i), [1]=(u10r,u10i,u11r,u11i)
__device__ float4 g_gates[NL * NQ][2];

__global__ void gate_prep_kernel(const float* __restrict__ w)
{
    int t = threadIdx.x;
    if (t < NL * NQ) {
        float phi = w[t * 3 + 0];
        float th  = w[t * 3 + 1];
        float om  = w[t * 3 + 2];
        float ch = cosf(th * 0.5f);
        float sh = sinf(th * 0.5f);
        float ap = 0.5f * (phi + om);
        float am = 0.5f * (phi - om);
        float ca, sa, cb, sb;
        sincosf(ap, &sa, &ca);
        sincosf(am, &sb, &cb);
        // u00 = e^{-i ap} ch ; u01 = -e^{+i am} sh ; u10 = e^{-i am} sh ; u11 = e^{+i ap} ch
        g_gates[t][0] = make_float4( ca * ch, -sa * ch, -cb * sh, -sb * sh);
        g_gates[t][1] = make_float4( cb * sh, -sb * sh,  ca * ch,  sa * ch);
    }
}

__device__ __forceinline__ int par(unsigned v) { return __popc(v) & 1; }

// Generalized butterfly gate over XOR-mask (LM: lane bits, RM: register bits),
// with role bit = parity(lane & RHOL) ^ parity(r & RHOR).
// role==0 row: new = u00*own + u01*other ; role==1 row: new = u11*own + u10*other.
template <int LM, int RM, int RHOL, int RHOR>
__device__ __forceinline__ void apply_gate(float* re, float* im, int lane,
                                           float4 ga, float4 gb)
{
    const bool lp = (__popc(lane & RHOL) & 1) != 0;
    // coefficient sets: index by cpar(r) = parity(r & RHOR); role = lp ^ cpar
    const float c0r = lp ? gb.z : ga.x;
    const float c0i = lp ? gb.w : ga.y;
    const float d0r = lp ? gb.x : ga.z;
    const float d0i = lp ? gb.y : ga.w;
    const float c1r = lp ? ga.x : gb.z;
    const float c1i = lp ? ga.y : gb.w;
    const float d1r = lp ? ga.z : gb.x;
    const float d1i = lp ? ga.w : gb.y;

    if (RM == 0) {
        // lane-only exchange: partner = other lane, same register
#pragma unroll
        for (int r = 0; r < 32; r++) {
            float ore = __shfl_xor_sync(0xffffffffu, re[r], LM);
            float oim = __shfl_xor_sync(0xffffffffu, im[r], LM);
            const bool cp = par(r & RHOR);
            const float cr = cp ? c1r : c0r, ci = cp ? c1i : c0i;
            const float dr = cp ? d1r : d0r, di = cp ? d1i : d0i;
            const float sr = re[r], si = im[r];
            re[r] = cr * sr - ci * si + dr * ore - di * oim;
            im[r] = cr * si + ci * sr + dr * oim + di * ore;
        }
    } else {
        const int PB = RM & (-RM);
#pragma unroll
        for (int r0 = 0; r0 < 32; r0++) {
            if ((r0 & PB) == 0) {
                const int r1 = r0 ^ RM;
                const float a0r = re[r0], a0i = im[r0];
                const float a1r = re[r1], a1i = im[r1];
                float o0r, o0i, o1r, o1i;
                if (LM != 0) {
                    o0r = __shfl_xor_sync(0xffffffffu, a1r, LM);
                    o0i = __shfl_xor_sync(0xffffffffu, a1i, LM);
                    o1r = __shfl_xor_sync(0xffffffffu, a0r, LM);
                    o1i = __shfl_xor_sync(0xffffffffu, a0i, LM);
                } else {
                    o0r = a1r; o0i = a1i; o1r = a0r; o1i = a0i;
                }
                {
                    const bool cp = par(r0 & RHOR);
                    const float cr = cp ? c1r : c0r, ci = cp ? c1i : c0i;
                    const float dr = cp ? d1r : d0r, di = cp ? d1i : d0i;
                    re[r0] = cr * a0r - ci * a0i + dr * o0r - di * o0i;
                    im[r0] = cr * a0i + ci * a0r + dr * o0i + di * o0r;
                }
                {
                    const bool cp = par(r1 & RHOR);
                    const float cr = cp ? c1r : c0r, ci = cp ? c1i : c0i;
                    const float dr = cp ? d1r : d0r, di = cp ? d1i : d0i;
                    re[r1] = cr * a1r - ci * a1i + dr * o1r - di * o1i;
                    im[r1] = cr * a1i + ci * a1r + dr * o1i + di * o1r;
                }
            }
        }
    }
}

// Measurement parity masks: final M rows, split into (lane mask, reg mask).
__device__ __constant__ const int Z_L[10] = { 3,  1, 19, 6, 12, 25, 19,  6, 12, 25};
__device__ __constant__ const int Z_R[10] = { 6, 19, 31, 0, 31, 16,  7, 12, 25, 19};

__global__ __launch_bounds__(NTHREADS, 2)
void qsim_reg_kernel(const float* __restrict__ x, float* __restrict__ out, int B)
{
    const int lane = threadIdx.x & 31;
    const int warp = threadIdx.x >> 5;
    const int b = blockIdx.x * WPB + warp;
    if (b >= B) return;

    // Physical index p = lane*32 + r (bit 9..5 = lane, bit 4..0 = r).
    float re[32], im[32];

    // ---- Load + normalize ----
    const float4* xb = (const float4*)(x + (size_t)b * DIMQ + lane * 32);
    float ss = 0.0f;
#pragma unroll
    for (int j = 0; j < 8; j++) {
        float4 v = xb[j];
        re[4 * j + 0] = v.x; re[4 * j + 1] = v.y;
        re[4 * j + 2] = v.z; re[4 * j + 3] = v.w;
        ss += v.x * v.x + v.y * v.y + v.z * v.z + v.w * v.w;
    }
#pragma unroll
    for (int o = 16; o > 0; o >>= 1)
        ss += __shfl_xor_sync(0xffffffffu, ss, o);
    const float inv = rsqrtf(ss);
#pragma unroll
    for (int r = 0; r < 32; r++) { re[r] *= inv; im[r] = 0.0f; }

    // ---- Layer 1 rots (M = I): wire q<5 -> lane bit 4-q ; q>=5 -> reg bit 9-q ----
    {
        float4 ga, gb;
#define G(i) ga = __ldg(&g_gates[i][0]); gb = __ldg(&g_gates[i][1])
        G(0); apply_gate<16, 0, 16, 0>(re, im, lane, ga, gb);
        G(1); apply_gate< 8, 0,  8, 0>(re, im, lane, ga, gb);
        G(2); apply_gate< 4, 0,  4, 0>(re, im, lane, ga, gb);
        G(3); apply_gate< 2, 0,  2, 0>(re, im, lane, ga, gb);
        G(4); apply_gate< 1, 0,  1, 0>(re, im, lane, ga, gb);
        G(5); apply_gate< 0,16,  0,16>(re, im, lane, ga, gb);
        G(6); apply_gate< 0, 8,  0, 8>(re, im, lane, ga, gb);
        G(7); apply_gate< 0, 4,  0, 4>(re, im, lane, ga, gb);
        G(8); apply_gate< 0, 2,  0, 2>(re, im, lane, ga, gb);
        G(9); apply_gate< 0, 1,  0, 1>(re, im, lane, ga, gb);

        // ---- Layer 1 CNOT ring (r=1): absorbed into M. Layer 2 rots use
        // masks m_q = M^-1 e_q and role masks rho_q = row_q(M). ----
        G(10); apply_gate<24, 0, 15, 31>(re, im, lane, ga, gb);
        G(11); apply_gate<12, 0, 24,  0>(re, im, lane, ga, gb);
        G(12); apply_gate< 6, 0, 28,  0>(re, im, lane, ga, gb);
        G(13); apply_gate< 3, 0, 30,  0>(re, im, lane, ga, gb);
        G(14); apply_gate< 1,16, 31,  0>(re, im, lane, ga, gb);
        G(15); apply_gate< 0,24, 31, 16>(re, im, lane, ga, gb);
        G(16); apply_gate< 0,12, 31, 24>(re, im, lane, ga, gb);
        G(17); apply_gate< 0, 6, 31, 28>(re, im, lane, ga, gb);
        G(18); apply_gate< 0, 3, 31, 30>(re, im, lane, ga, gb);
        G(19); apply_gate<24, 1, 31, 31>(re, im, lane, ga, gb);
#undef G
        // ---- Layer 2 CNOT ring (r=2): absorbed into final measurement masks. ----
    }

    // ---- probs -> PauliZ expvals with permuted sign masks ----
    float acc[10];
#pragma unroll
    for (int i = 0; i < 10; i++) acc[i] = 0.0f;
#pragma unroll
    for (int r = 0; r < 32; r++) {
        const float pr = re[r] * re[r] + im[r] * im[r];
#pragma unroll
        for (int i = 0; i < 10; i++) {
            if (par(r & Z_R[i])) acc[i] -= pr; else acc[i] += pr;
        }
    }
#pragma unroll
    for (int i = 0; i < 10; i++)
        if (par(lane & Z_L[i])) acc[i] = -acc[i];
#pragma unroll
    for (int o = 16; o > 0; o >>= 1) {
#pragma unroll
        for (int i = 0; i < 10; i++)
            acc[i] += __shfl_xor_sync(0xffffffffu, acc[i], o);
    }
#pragma unroll
    for (int i = 0; i < 10; i++)
        if (lane == i) out[(size_t)b * NQ + i] = acc[i];
}

extern "C" void kernel_launch(void* const* d_in, const int* in_sizes, int n_in,
                              void* d_out, int out_size)
{
    const float* x;
    const float* w;
    int xsize;
    if (in_sizes[0] == NL * NQ * 3) {
        w = (const float*)d_in[0];
        x = (const float*)d_in[1];
        xsize = in_sizes[1];
    } else {
        x = (const float*)d_in[0];
        w = (const float*)d_in[1];
        xsize = in_sizes[0];
    }
    const int B = xsize / DIMQ;
    float* out = (float*)d_out;
    gate_prep_kernel<<<1, 32>>>(w);
    qsim_reg_kernel<<<(B + WPB - 1) / WPB, NTHREADS>>>(x, out, B);
    (void)n_in; (void)out_size;
}

// round 7
// speedup vs baseline: 3.9054x; 1.1239x over previous
#include <cuda_runtime.h>
#include <math.h>

#define NQ 10
#define DIMQ 1024
#define NL 2
#define WPB 8
#define NTHREADS (WPB * 32)

typedef unsigned long long u64;

// Precomputed 2x2 gate matrices: [gate][0]=(u00r,u00i,u01r,u01i), [1]=(u10r,u10i,u11r,u11i)
__device__ float4 g_gates[NL * NQ][2];

__global__ void gate_prep_kernel(const float* __restrict__ w)
{
    int t = threadIdx.x;
    if (t < NL * NQ) {
        float phi = w[t * 3 + 0];
        float th  = w[t * 3 + 1];
        float om  = w[t * 3 + 2];
        float ch = cosf(th * 0.5f);
        float sh = sinf(th * 0.5f);
        float ap = 0.5f * (phi + om);
        float am = 0.5f * (phi - om);
        float ca, sa, cb, sb;
        sincosf(ap, &sa, &ca);
        sincosf(am, &sb, &cb);
        g_gates[t][0] = make_float4( ca * ch, -sa * ch, -cb * sh, -sb * sh);
        g_gates[t][1] = make_float4( cb * sh, -sb * sh,  ca * ch,  sa * ch);
    }
}

// ---- f32x2 packed helpers ----
__device__ __forceinline__ u64 pk(float lo, float hi) {
    u64 r; asm("mov.b64 %0, {%1, %2};" : "=l"(r) : "f"(lo), "f"(hi)); return r;
}
__device__ __forceinline__ float2 upk(u64 v) {
    float lo, hi; asm("mov.b64 {%0, %1}, %2;" : "=f"(lo), "=f"(hi) : "l"(v));
    return make_float2(lo, hi);
}
__device__ __forceinline__ u64 fma2(u64 a, u64 b, u64 c) {
    u64 d; asm("fma.rn.f32x2 %0, %1, %2, %3;" : "=l"(d) : "l"(a), "l"(b), "l"(c)); return d;
}
__device__ __forceinline__ u64 mul2(u64 a, u64 b) {
    u64 d; asm("mul.rn.f32x2 %0, %1, %2;" : "=l"(d) : "l"(a), "l"(b)); return d;
}
__device__ __forceinline__ u64 swap64(u64 v) {
    float2 f = upk(v); return pk(f.y, f.x);
}
__device__ __forceinline__ int par(unsigned v) { return __popc(v) & 1; }
__host__ __device__ constexpr int parc(int v) {
    int p = 0;
    for (int i = 0; i < 10; i++) p ^= (v >> i) & 1;
    return p;
}

// Generalized packed butterfly gate. Amplitude index: lane*32 + 2*k + e,
// e in {0,1} is the f32x2 element. Mask = (LM lane bits, RM reg bits).
// Role bit = parity(lane&RHOL) ^ parity(r&RHOR).
template <int LM, int RM, int RHOL, int RHOR>
__device__ __forceinline__ void gate_p(u64* re, u64* im, int lane,
                                       float4 ga, float4 gb)
{
    const bool lp = (__popc(lane & RHOL) & 1) != 0;
    // coefficients for element parity p (role = lp ^ p):
    const float c0r = lp ? gb.z : ga.x, c0i = lp ? gb.w : ga.y;  // own, p=0
    const float d0r = lp ? gb.x : ga.z, d0i = lp ? gb.y : ga.w;  // other, p=0
    const float c1r = lp ? ga.x : gb.z, c1i = lp ? ga.y : gb.w;  // own, p=1
    const float d1r = lp ? ga.z : gb.x, d1i = lp ? ga.w : gb.y;  // other, p=1

    constexpr int flip = RHOR & 1;
    // packed coefficient sets for base parity b: elements (b, b^flip)
#define MK(b, a0, a1) ((b) ? (a1) : (a0))
    const u64 CR0  = pk(c0r, MK(flip, c0r, c1r));
    const u64 CI0  = pk(c0i, MK(flip, c0i, c1i));
    const u64 CIn0 = pk(-c0i, MK(flip, -c0i, -c1i));
    const u64 DR0  = pk(d0r, MK(flip, d0r, d1r));
    const u64 DI0  = pk(d0i, MK(flip, d0i, d1i));
    const u64 DIn0 = pk(-d0i, MK(flip, -d0i, -d1i));
    const u64 CR1  = pk(c1r, MK(flip, c1r, c0r));
    const u64 CI1  = pk(c1i, MK(flip, c1i, c0i));
    const u64 CIn1 = pk(-c1i, MK(flip, -c1i, -c0i));
    const u64 DR1  = pk(d1r, MK(flip, d1r, d0r));
    const u64 DI1  = pk(d1i, MK(flip, d1i, d0i));
    const u64 DIn1 = pk(-d1i, MK(flip, -d1i, -d0i));
#undef MK

    constexpr int RMH = RM >> 1;   // pack-level xor
    constexpr int SW  = RM & 1;    // intra-pack element swap

    if (RMH == 0) {
        // partner is same pack index: swap and/or lane shuffle
#pragma unroll
        for (int k = 0; k < 16; k++) {
            const int b = parc((2 * k) & RHOR);
            const u64 cr = b ? CR1 : CR0, ci = b ? CI1 : CI0, cin = b ? CIn1 : CIn0;
            const u64 dr = b ? DR1 : DR0, di = b ? DI1 : DI0, din = b ? DIn1 : DIn0;
            u64 vR = re[k], vI = im[k];
            u64 oR = vR, oI = vI;
            if (SW)  { oR = swap64(oR); oI = swap64(oI); }
            if (LM != 0) {
                oR = __shfl_xor_sync(0xffffffffu, oR, LM);
                oI = __shfl_xor_sync(0xffffffffu, oI, LM);
            }
            re[k] = fma2(cr, vR, fma2(cin, vI, fma2(dr, oR, mul2(din, oI))));
            im[k] = fma2(cr, vI, fma2(ci,  vR, fma2(dr, oI, mul2(di,  oR))));
        }
    } else {
        constexpr int PB = RMH & (-RMH);
#pragma unroll
        for (int k0 = 0; k0 < 16; k0++) {
            if ((k0 & PB) == 0) {
                const int k1 = k0 ^ RMH;
                const int b0 = parc((2 * k0) & RHOR);
                const int b1 = parc((2 * k1) & RHOR);
                u64 v0R = re[k0], v0I = im[k0];
                u64 v1R = re[k1], v1I = im[k1];
                u64 o0R = v1R, o0I = v1I, o1R = v0R, o1I = v0I;
                if (SW) {
                    o0R = swap64(o0R); o0I = swap64(o0I);
                    o1R = swap64(o1R); o1I = swap64(o1I);
                }
                if (LM != 0) {
                    o0R = __shfl_xor_sync(0xffffffffu, o0R, LM);
                    o0I = __shfl_xor_sync(0xffffffffu, o0I, LM);
                    o1R = __shfl_xor_sync(0xffffffffu, o1R, LM);
                    o1I = __shfl_xor_sync(0xffffffffu, o1I, LM);
                }
                {
                    const u64 cr = b0 ? CR1 : CR0, ci = b0 ? CI1 : CI0, cin = b0 ? CIn1 : CIn0;
                    const u64 dr = b0 ? DR1 : DR0, di = b0 ? DI1 : DI0, din = b0 ? DIn1 : DIn0;
                    re[k0] = fma2(cr, v0R, fma2(cin, v0I, fma2(dr, o0R, mul2(din, o0I))));
                    im[k0] = fma2(cr, v0I, fma2(ci,  v0R, fma2(dr, o0I, mul2(di,  o0R))));
                }
                {
                    const u64 cr = b1 ? CR1 : CR0, ci = b1 ? CI1 : CI0, cin = b1 ? CIn1 : CIn0;
                    const u64 dr = b1 ? DR1 : DR0, di = b1 ? DI1 : DI0, din = b1 ? DIn1 : DIn0;
                    re[k1] = fma2(cr, v1R, fma2(cin, v1I, fma2(dr, o1R, mul2(din, o1I))));
                    im[k1] = fma2(cr, v1I, fma2(ci,  v1R, fma2(dr, o1I, mul2(di,  o1R))));
                }
            }
        }
    }
}

__global__ __launch_bounds__(NTHREADS, 2)
void qsim_reg_kernel(const float* __restrict__ x, float* __restrict__ out, int B)
{
    const int lane = threadIdx.x & 31;
    const int warp = threadIdx.x >> 5;
    const int b = blockIdx.x * WPB + warp;
    if (b >= B) return;

    u64 re[16], im[16];  // re[k] = (amp[2k].re, amp[2k+1].re) packed f32x2

    // ---- Load + normalize ----
    const ulonglong2* xb = (const ulonglong2*)(x + (size_t)b * DIMQ + lane * 32);
    u64 ssP = 0ull;
#pragma unroll
    for (int j = 0; j < 8; j++) {
        ulonglong2 v = xb[j];
        re[2 * j + 0] = v.x;
        re[2 * j + 1] = v.y;
        ssP = fma2(v.x, v.x, ssP);
        ssP = fma2(v.y, v.y, ssP);
    }
    float2 ssf = upk(ssP);
    float ss = ssf.x + ssf.y;
#pragma unroll
    for (int o = 16; o > 0; o >>= 1)
        ss += __shfl_xor_sync(0xffffffffu, ss, o);
    const float inv = rsqrtf(ss);
    const u64 INV = pk(inv, inv);
#pragma unroll
    for (int k = 0; k < 16; k++) { re[k] = mul2(re[k], INV); im[k] = 0ull; }

    // ---- Circuit (CNOTs absorbed into masks/roles; see round-4 derivation) ----
    {
        float4 ga, gb;
#define G(i) ga = __ldg(&g_gates[i][0]); gb = __ldg(&g_gates[i][1])
        G(0);  gate_p<16, 0, 16,  0>(re, im, lane, ga, gb);
        G(1);  gate_p< 8, 0,  8,  0>(re, im, lane, ga, gb);
        G(2);  gate_p< 4, 0,  4,  0>(re, im, lane, ga, gb);
        G(3);  gate_p< 2, 0,  2,  0>(re, im, lane, ga, gb);
        G(4);  gate_p< 1, 0,  1,  0>(re, im, lane, ga, gb);
        G(5);  gate_p< 0,16,  0, 16>(re, im, lane, ga, gb);
        G(6);  gate_p< 0, 8,  0,  8>(re, im, lane, ga, gb);
        G(7);  gate_p< 0, 4,  0,  4>(re, im, lane, ga, gb);
        G(8);  gate_p< 0, 2,  0,  2>(re, im, lane, ga, gb);
        G(9);  gate_p< 0, 1,  0,  1>(re, im, lane, ga, gb);
        G(10); gate_p<24, 0, 15, 31>(re, im, lane, ga, gb);
        G(11); gate_p<12, 0, 24,  0>(re, im, lane, ga, gb);
        G(12); gate_p< 6, 0, 28,  0>(re, im, lane, ga, gb);
        G(13); gate_p< 3, 0, 30,  0>(re, im, lane, ga, gb);
        G(14); gate_p< 1,16, 31,  0>(re, im, lane, ga, gb);
        G(15); gate_p< 0,24, 31, 16>(re, im, lane, ga, gb);
        G(16); gate_p< 0,12, 31, 24>(re, im, lane, ga, gb);
        G(17); gate_p< 0, 6, 31, 28>(re, im, lane, ga, gb);
        G(18); gate_p< 0, 3, 31, 30>(re, im, lane, ga, gb);
        G(19); gate_p<24, 1, 31, 31>(re, im, lane, ga, gb);
#undef G
    }

    // ---- probs -> PauliZ expvals (packed sign-accumulate) ----
    // Measurement masks (final linear map rows) as LITERALS (no device array):
    //   i:      0    1    2    3    4    5    6    7    8    9
    //   Z_L:    3    1   19    6   12   25   19    6   12   25
    //   Z_R:    6   19   31    0   31   16    7   12   25   19
    const u64 SPP = pk( 1.0f,  1.0f);
    const u64 SPM = pk( 1.0f, -1.0f);
    const u64 SMP = pk(-1.0f,  1.0f);
    const u64 SMM = pk(-1.0f, -1.0f);
    u64 acc[10];
#pragma unroll
    for (int i = 0; i < 10; i++) acc[i] = 0ull;

#define ACCI(i, ZR) { \
        const int s0 = parc((2 * k) & (ZR)); \
        const int s1 = parc((2 * k + 1) & (ZR)); \
        const u64 sg = s0 ? ((s1) ? SMM : SMP) : ((s1) ? SPM : SPP); \
        acc[i] = fma2(sg, pr, acc[i]); }

#pragma unroll
    for (int k = 0; k < 16; k++) {
        const u64 pr = fma2(re[k], re[k], mul2(im[k], im[k]));
        ACCI(0,  6)
        ACCI(1, 19)
        ACCI(2, 31)
        ACCI(3,  0)
        ACCI(4, 31)
        ACCI(5, 16)
        ACCI(6,  7)
        ACCI(7, 12)
        ACCI(8, 25)
        ACCI(9, 19)
    }
#undef ACCI

    float av[10];
#define SGNL(i, ZL) { \
        float2 a = upk(acc[i]); \
        float v = a.x + a.y; \
        if (par((unsigned)(lane & (ZL)))) v = -v; \
        av[i] = v; }
    SGNL(0,  3)
    SGNL(1,  1)
    SGNL(2, 19)
    SGNL(3,  6)
    SGNL(4, 12)
    SGNL(5, 25)
    SGNL(6, 19)
    SGNL(7,  6)
    SGNL(8, 12)
    SGNL(9, 25)
#undef SGNL

#pragma unroll
    for (int o = 16; o > 0; o >>= 1) {
#pragma unroll
        for (int i = 0; i < 10; i++)
            av[i] += __shfl_xor_sync(0xffffffffu, av[i], o);
    }
#pragma unroll
    for (int i = 0; i < 10; i++)
        if (lane == i) out[(size_t)b * NQ + i] = av[i];
}

extern "C" void kernel_launch(void* const* d_in, const int* in_sizes, int n_in,
                              void* d_out, int out_size)
{
    const float* x;
    const float* w;
    int xsize;
    if (in_sizes[0] == NL * NQ * 3) {
        w = (const float*)d_in[0];
        x = (const float*)d_in[1];
        xsize = in_sizes[1];
    } else {
        x = (const float*)d_in[0];
        w = (const float*)d_in[1];
        xsize = in_sizes[0];
    }
    const int B = xsize / DIMQ;
    float* out = (float*)d_out;
    gate_prep_kernel<<<1, 32>>>(w);
    qsim_reg_kernel<<<(B + WPB - 1) / WPB, NTHREADS>>>(x, out, B);
    (void)n_in; (void)out_size;
}

// round 8
// speedup vs baseline: 4.1097x; 1.0523x over previous
#include <cuda_runtime.h>
#include <math.h>

#define NQ 10
#define DIMQ 1024
#define NL 2
#define WPB 8
#define NTHREADS (WPB * 32)

typedef unsigned long long u64;

// Precomputed 2x2 gate matrices: [gate][0]=(u00r,u00i,u01r,u01i), [1]=(u10r,u10i,u11r,u11i)
__device__ float4 g_gates[NL * NQ][2];

__global__ void gate_prep_kernel(const float* __restrict__ w)
{
    int t = threadIdx.x;
    if (t < NL * NQ) {
        float phi = w[t * 3 + 0];
        float th  = w[t * 3 + 1];
        float om  = w[t * 3 + 2];
        float ch = cosf(th * 0.5f);
        float sh = sinf(th * 0.5f);
        float ap = 0.5f * (phi + om);
        float am = 0.5f * (phi - om);
        float ca, sa, cb, sb;
        sincosf(ap, &sa, &ca);
        sincosf(am, &sb, &cb);
        g_gates[t][0] = make_float4( ca * ch, -sa * ch, -cb * sh, -sb * sh);
        g_gates[t][1] = make_float4( cb * sh, -sb * sh,  ca * ch,  sa * ch);
    }
}

// ---- f32x2 packed helpers ----
__device__ __forceinline__ u64 pk(float lo, float hi) {
    u64 r; asm("mov.b64 %0, {%1, %2};" : "=l"(r) : "f"(lo), "f"(hi)); return r;
}
__device__ __forceinline__ float2 upk(u64 v) {
    float lo, hi; asm("mov.b64 {%0, %1}, %2;" : "=f"(lo), "=f"(hi) : "l"(v));
    return make_float2(lo, hi);
}
__device__ __forceinline__ u64 fma2(u64 a, u64 b, u64 c) {
    u64 d; asm("fma.rn.f32x2 %0, %1, %2, %3;" : "=l"(d) : "l"(a), "l"(b), "l"(c)); return d;
}
__device__ __forceinline__ u64 mul2(u64 a, u64 b) {
    u64 d; asm("mul.rn.f32x2 %0, %1, %2;" : "=l"(d) : "l"(a), "l"(b)); return d;
}
__device__ __forceinline__ u64 add2(u64 a, u64 b) {
    u64 d; asm("add.rn.f32x2 %0, %1, %2;" : "=l"(d) : "l"(a), "l"(b)); return d;
}
__device__ __forceinline__ u64 sub2(u64 a, u64 b) {
    u64 d; asm("sub.rn.f32x2 %0, %1, %2;" : "=l"(d) : "l"(a), "l"(b)); return d;
}
__device__ __forceinline__ u64 swap64(u64 v) {
    float2 f = upk(v); return pk(f.y, f.x);
}
__device__ __forceinline__ int par(unsigned v) { return __popc(v) & 1; }
__host__ __device__ constexpr int parc(int v) {
    int p = 0;
    for (int i = 0; i < 10; i++) p ^= (v >> i) & 1;
    return p;
}

// Generalized packed butterfly gate. Amplitude index: lane*32 + 2*k + e,
// e in {0,1} is the f32x2 element. Mask = (LM lane bits, RM reg bits).
// Role bit = parity(lane&RHOL) ^ parity(r&RHOR).
// FMA chains are ordered own-terms-innermost so the shuffle-dependent
// multiplies land at the end of the dependency chain.
template <int LM, int RM, int RHOL, int RHOR>
__device__ __forceinline__ void gate_p(u64* re, u64* im, int lane,
                                       float4 ga, float4 gb)
{
    const bool lp = (__popc(lane & RHOL) & 1) != 0;
    const float c0r = lp ? gb.z : ga.x, c0i = lp ? gb.w : ga.y;  // own, p=0
    const float d0r = lp ? gb.x : ga.z, d0i = lp ? gb.y : ga.w;  // other, p=0
    const float c1r = lp ? ga.x : gb.z, c1i = lp ? ga.y : gb.w;  // own, p=1
    const float d1r = lp ? ga.z : gb.x, d1i = lp ? ga.w : gb.y;  // other, p=1

    constexpr int flip = RHOR & 1;
#define MK(b, a0, a1) ((b) ? (a1) : (a0))
    const u64 CR0  = pk(c0r, MK(flip, c0r, c1r));
    const u64 CI0  = pk(c0i, MK(flip, c0i, c1i));
    const u64 CIn0 = pk(-c0i, MK(flip, -c0i, -c1i));
    const u64 DR0  = pk(d0r, MK(flip, d0r, d1r));
    const u64 DI0  = pk(d0i, MK(flip, d0i, d1i));
    const u64 DIn0 = pk(-d0i, MK(flip, -d0i, -d1i));
    const u64 CR1  = pk(c1r, MK(flip, c1r, c0r));
    const u64 CI1  = pk(c1i, MK(flip, c1i, c0i));
    const u64 CIn1 = pk(-c1i, MK(flip, -c1i, -c0i));
    const u64 DR1  = pk(d1r, MK(flip, d1r, d0r));
    const u64 DI1  = pk(d1i, MK(flip, d1i, d0i));
    const u64 DIn1 = pk(-d1i, MK(flip, -d1i, -d0i));
#undef MK

    constexpr int RMH = RM >> 1;   // pack-level xor
    constexpr int SW  = RM & 1;    // intra-pack element swap

    if (RMH == 0) {
#pragma unroll
        for (int k = 0; k < 16; k++) {
            const int b = parc((2 * k) & RHOR);
            const u64 cr = b ? CR1 : CR0, ci = b ? CI1 : CI0, cin = b ? CIn1 : CIn0;
            const u64 dr = b ? DR1 : DR0, di = b ? DI1 : DI0, din = b ? DIn1 : DIn0;
            u64 vR = re[k], vI = im[k];
            u64 oR = vR, oI = vI;
            if (SW)  { oR = swap64(oR); oI = swap64(oI); }
            if (LM != 0) {
                oR = __shfl_xor_sync(0xffffffffu, oR, LM);
                oI = __shfl_xor_sync(0xffffffffu, oI, LM);
            }
            // own terms innermost; shuffle-dependent terms last
            re[k] = fma2(dr, oR, fma2(din, oI, fma2(cr, vR, mul2(cin, vI))));
            im[k] = fma2(dr, oI, fma2(di,  oR, fma2(cr, vI, mul2(ci,  vR))));
        }
    } else {
        constexpr int PB = RMH & (-RMH);
#pragma unroll
        for (int k0 = 0; k0 < 16; k0++) {
            if ((k0 & PB) == 0) {
                const int k1 = k0 ^ RMH;
                const int b0 = parc((2 * k0) & RHOR);
                const int b1 = parc((2 * k1) & RHOR);
                u64 v0R = re[k0], v0I = im[k0];
                u64 v1R = re[k1], v1I = im[k1];
                u64 o0R = v1R, o0I = v1I, o1R = v0R, o1I = v0I;
                if (SW) {
                    o0R = swap64(o0R); o0I = swap64(o0I);
                    o1R = swap64(o1R); o1I = swap64(o1I);
                }
                if (LM != 0) {
                    o0R = __shfl_xor_sync(0xffffffffu, o0R, LM);
                    o0I = __shfl_xor_sync(0xffffffffu, o0I, LM);
                    o1R = __shfl_xor_sync(0xffffffffu, o1R, LM);
                    o1I = __shfl_xor_sync(0xffffffffu, o1I, LM);
                }
                {
                    const u64 cr = b0 ? CR1 : CR0, ci = b0 ? CI1 : CI0, cin = b0 ? CIn1 : CIn0;
                    const u64 dr = b0 ? DR1 : DR0, di = b0 ? DI1 : DI0, din = b0 ? DIn1 : DIn0;
                    re[k0] = fma2(dr, o0R, fma2(din, o0I, fma2(cr, v0R, mul2(cin, v0I))));
                    im[k0] = fma2(dr, o0I, fma2(di,  o0R, fma2(cr, v0I, mul2(ci,  v0R))));
                }
                {
                    const u64 cr = b1 ? CR1 : CR0, ci = b1 ? CI1 : CI0, cin = b1 ? CIn1 : CIn0;
                    const u64 dr = b1 ? DR1 : DR0, di = b1 ? DI1 : DI0, din = b1 ? DIn1 : DIn0;
                    re[k1] = fma2(dr, o1R, fma2(din, o1I, fma2(cr, v1R, mul2(cin, v1I))));
                    im[k1] = fma2(dr, o1I, fma2(di,  o1R, fma2(cr, v1I, mul2(ci,  v1R))));
                }
            }
        }
    }
}

__global__ __launch_bounds__(NTHREADS, 2)
void qsim_reg_kernel(const float* __restrict__ x, float* __restrict__ out, int B)
{
    const int lane = threadIdx.x & 31;
    const int warp = threadIdx.x >> 5;
    const int b = blockIdx.x * WPB + warp;
    if (b >= B) return;

    u64 re[16], im[16];  // re[k] = (amp[2k].re, amp[2k+1].re) packed f32x2

    // ---- Load raw (normalization folded into gate 0) ----
    const ulonglong2* xb = (const ulonglong2*)(x + (size_t)b * DIMQ + lane * 32);
    u64 ssP = 0ull;
#pragma unroll
    for (int j = 0; j < 8; j++) {
        ulonglong2 v = xb[j];
        re[2 * j + 0] = v.x;
        re[2 * j + 1] = v.y;
        ssP = fma2(v.x, v.x, ssP);
        ssP = fma2(v.y, v.y, ssP);
    }
    float2 ssf = upk(ssP);
    float ss = ssf.x + ssf.y;
#pragma unroll
    for (int o = 16; o > 0; o >>= 1)
        ss += __shfl_xor_sync(0xffffffffu, ss, o);
    const float inv = rsqrtf(ss);

    // ---- Gate 0 specialized: state is real (im == 0); fold inv into coeffs.
    //      LM=16, RHOL=16, RHOR=0. Needs only the re shuffle. ----
    {
        const float4 ga = __ldg(&g_gates[0][0]);
        const float4 gb = __ldg(&g_gates[0][1]);
        const bool lp = (lane & 16) != 0;
        const float crs = (lp ? gb.z : ga.x) * inv;
        const float cis = (lp ? gb.w : ga.y) * inv;
        const float drs = (lp ? gb.x : ga.z) * inv;
        const float dis = (lp ? gb.y : ga.w) * inv;
        const u64 CR = pk(crs, crs);
        const u64 CI = pk(cis, cis);
        const u64 DR = pk(drs, drs);
        const u64 DI = pk(dis, dis);
#pragma unroll
        for (int k = 0; k < 16; k++) {
            const u64 vR = re[k];
            const u64 oR = __shfl_xor_sync(0xffffffffu, vR, 16);
            re[k] = fma2(DR, oR, mul2(CR, vR));
            im[k] = fma2(DI, oR, mul2(CI, vR));
        }
    }

    // ---- Remaining circuit (CNOTs absorbed into masks/roles) ----
    {
        float4 ga, gb;
#define G(i) ga = __ldg(&g_gates[i][0]); gb = __ldg(&g_gates[i][1])
        G(1);  gate_p< 8, 0,  8,  0>(re, im, lane, ga, gb);
        G(2);  gate_p< 4, 0,  4,  0>(re, im, lane, ga, gb);
        G(3);  gate_p< 2, 0,  2,  0>(re, im, lane, ga, gb);
        G(4);  gate_p< 1, 0,  1,  0>(re, im, lane, ga, gb);
        G(5);  gate_p< 0,16,  0, 16>(re, im, lane, ga, gb);
        G(6);  gate_p< 0, 8,  0,  8>(re, im, lane, ga, gb);
        G(7);  gate_p< 0, 4,  0,  4>(re, im, lane, ga, gb);
        G(8);  gate_p< 0, 2,  0,  2>(re, im, lane, ga, gb);
        G(9);  gate_p< 0, 1,  0,  1>(re, im, lane, ga, gb);
        G(10); gate_p<24, 0, 15, 31>(re, im, lane, ga, gb);
        G(11); gate_p<12, 0, 24,  0>(re, im, lane, ga, gb);
        G(12); gate_p< 6, 0, 28,  0>(re, im, lane, ga, gb);
        G(13); gate_p< 3, 0, 30,  0>(re, im, lane, ga, gb);
        G(14); gate_p< 1,16, 31,  0>(re, im, lane, ga, gb);
        G(15); gate_p< 0,24, 31, 16>(re, im, lane, ga, gb);
        G(16); gate_p< 0,12, 31, 24>(re, im, lane, ga, gb);
        G(17); gate_p< 0, 6, 31, 28>(re, im, lane, ga, gb);
        G(18); gate_p< 0, 3, 31, 30>(re, im, lane, ga, gb);
        G(19); gate_p<24, 1, 31, 31>(re, im, lane, ga, gb);
#undef G
    }

    // ---- probs -> signed sums via 4-stage WHT over pack index ----
    // Measurement masks (lane, reg): Z_L={3,1,19,6,12,25,19,6,12,25},
    //                                Z_R={6,19,31,0,31,16,7,12,25,19}
    u64 W[16];
#pragma unroll
    for (int k = 0; k < 16; k++)
        W[k] = fma2(re[k], re[k], mul2(im[k], im[k]));
#pragma unroll
    for (int s = 1; s < 16; s <<= 1) {
#pragma unroll
        for (int k = 0; k < 16; k++) {
            if ((k & s) == 0) {
                const u64 a = W[k], c = W[k | s];
                W[k] = add2(a, c);
                W[k | s] = sub2(a, c);
            }
        }
    }
    // W[mk] = (sum_k ±p_{2k}, sum_k ±p_{2k+1}); for reg-mask m: mk=m>>1,
    // fold elements with + if (m&1)==0 else -.
    float av[10];
    {
        float2 w3  = upk(W[3]);
        float2 w9  = upk(W[9]);
        float2 w15 = upk(W[15]);
        float2 w0  = upk(W[0]);
        float2 w8  = upk(W[8]);
        float2 w6  = upk(W[6]);
        float2 w12 = upk(W[12]);
        av[0] = w3.x  + w3.y;    // Z_R=6
        av[1] = w9.x  - w9.y;    // Z_R=19
        av[2] = w15.x - w15.y;   // Z_R=31
        av[3] = w0.x  + w0.y;    // Z_R=0
        av[4] = av[2];           // Z_R=31
        av[5] = w8.x  + w8.y;    // Z_R=16
        av[6] = w3.x  - w3.y;    // Z_R=7
        av[7] = w6.x  + w6.y;    // Z_R=12
        av[8] = w12.x - w12.y;   // Z_R=25
        av[9] = av[1];           // Z_R=19
    }
#define SGNL(i, ZL) if (par((unsigned)(lane & (ZL)))) av[i] = -av[i];
    SGNL(0,  3)
    SGNL(1,  1)
    SGNL(2, 19)
    SGNL(3,  6)
    SGNL(4, 12)
    SGNL(5, 25)
    SGNL(6, 19)
    SGNL(7,  6)
    SGNL(8, 12)
    SGNL(9, 25)
#undef SGNL

#pragma unroll
    for (int o = 16; o > 0; o >>= 1) {
#pragma unroll
        for (int i = 0; i < 10; i++)
            av[i] += __shfl_xor_sync(0xffffffffu, av[i], o);
    }
#pragma unroll
    for (int i = 0; i < 10; i++)
        if (lane == i) out[(size_t)b * NQ + i] = av[i];
}

extern "C" void kernel_launch(void* const* d_in, const int* in_sizes, int n_in,
                              void* d_out, int out_size)
{
    const float* x;
    const float* w;
    int xsize;
    if (in_sizes[0] == NL * NQ * 3) {
        w = (const float*)d_in[0];
        x = (const float*)d_in[1];
        xsize = in_sizes[1];
    } else {
        x = (const float*)d_in[0];
        w = (const float*)d_in[1];
        xsize = in_sizes[0];
    }
    const int B = xsize / DIMQ;
    float* out = (float*)d_out;
    gate_prep_kernel<<<1, 32>>>(w);
    qsim_reg_kernel<<<(B + WPB - 1) / WPB, NTHREADS>>>(x, out, B);
    (void)n_in; (void)out_size;
}

// round 9
// speedup vs baseline: 5.2633x; 1.2807x over previous
#include <cuda_runtime.h>
#include <math.h>

#define NQ 10
#define DIMQ 1024
#define NL 2
#define WPB 8
#define NTHREADS (WPB * 32)

typedef unsigned long long u64;

// RY coefficients: (cos(theta/2), sin(theta/2)) per gate
__device__ float2 g_ry[NL * NQ];
// Diagonal tables, packed f32x2 over pack layout idx = k*32 + lane,
// covering amplitudes p0 = lane*32 + 2k and p1 = p0 + 1.
__device__ u64 g_d1r[512], g_d1i[512];              // D_phi1 (cos, sin)
__device__ u64 g_dmr[512], g_dmi[512], g_dmin[512]; // D_mid (cos, sin, -sin)

// ---- f32x2 packed helpers ----
__device__ __forceinline__ u64 pk(float lo, float hi) {
    u64 r; asm("mov.b64 %0, {%1, %2};" : "=l"(r) : "f"(lo), "f"(hi)); return r;
}
__device__ __forceinline__ float2 upk(u64 v) {
    float lo, hi; asm("mov.b64 {%0, %1}, %2;" : "=f"(lo), "=f"(hi) : "l"(v));
    return make_float2(lo, hi);
}
__device__ __forceinline__ u64 fma2(u64 a, u64 b, u64 c) {
    u64 d; asm("fma.rn.f32x2 %0, %1, %2, %3;" : "=l"(d) : "l"(a), "l"(b), "l"(c)); return d;
}
__device__ __forceinline__ u64 mul2(u64 a, u64 b) {
    u64 d; asm("mul.rn.f32x2 %0, %1, %2;" : "=l"(d) : "l"(a), "l"(b)); return d;
}
__device__ __forceinline__ u64 add2(u64 a, u64 b) {
    u64 d; asm("add.rn.f32x2 %0, %1, %2;" : "=l"(d) : "l"(a), "l"(b)); return d;
}
__device__ __forceinline__ u64 sub2(u64 a, u64 b) {
    u64 d; asm("sub.rn.f32x2 %0, %1, %2;" : "=l"(d) : "l"(a), "l"(b)); return d;
}
__device__ __forceinline__ u64 swap64(u64 v) {
    float2 f = upk(v); return pk(f.y, f.x);
}
__device__ __forceinline__ int par(unsigned v) { return __popc(v) & 1; }
__host__ __device__ constexpr int parc(int v) {
    int p = 0;
    for (int i = 0; i < 10; i++) p ^= (v >> i) & 1;
    return p;
}

// ---- Prep: RY coeffs + diagonal tables ----
__global__ void prep_kernel(const float* __restrict__ w)
{
    __shared__ float cA[DIMQ], sA[DIMQ];
    const int t = threadIdx.x;

    if (t < NL * NQ) {
        float th = w[t * 3 + 1];
        g_ry[t] = make_float2(cosf(0.5f * th), sinf(0.5f * th));
    }

    // D_phi1: angle(p) = sum_q (bit_q(p) ? +0.5 : -0.5) * phi1_q, wire q -> bit 9-q
    {
        float a = 0.0f;
#pragma unroll
        for (int q = 0; q < NQ; q++) {
            int bit = (t >> (9 - q)) & 1;
            a += (bit ? 0.5f : -0.5f) * w[q * 3 + 0];
        }
        cA[t] = cosf(a); sA[t] = sinf(a);
    }
    __syncthreads();
    if (t < 512) {
        const int lane = t & 31, k = t >> 5;
        const int p0 = lane * 32 + 2 * k;
        g_d1r[t] = pk(cA[p0], cA[p0 + 1]);
        g_d1i[t] = pk(sA[p0], sA[p0 + 1]);
    }
    __syncthreads();

    // D_mid = D_omega1 (plain bits) * D_phi2 (rho parity masks from CNOT-ring-1 absorption)
    {
        const int rho[10] = {511, 768, 896, 960, 992, 1008, 1016, 1020, 1022, 1023};
        float a = 0.0f;
#pragma unroll
        for (int q = 0; q < NQ; q++) {
            int bit = (t >> (9 - q)) & 1;
            a += (bit ? 0.5f : -0.5f) * w[q * 3 + 2];
        }
#pragma unroll
        for (int q = 0; q < NQ; q++) {
            int pb = __popc(t & rho[q]) & 1;
            a += (pb ? 0.5f : -0.5f) * w[(NQ + q) * 3 + 0];
        }
        cA[t] = cosf(a); sA[t] = sinf(a);
    }
    __syncthreads();
    if (t < 512) {
        const int lane = t & 31, k = t >> 5;
        const int p0 = lane * 32 + 2 * k;
        g_dmr[t]  = pk(cA[p0],  cA[p0 + 1]);
        g_dmi[t]  = pk(sA[p0],  sA[p0 + 1]);
        g_dmin[t] = pk(-sA[p0], -sA[p0 + 1]);
    }
}

// Real-rotation butterfly over mask (LM lane bits, RM reg bits).
// role = par(lane&RHOL) ^ par(r&RHOR); role0: new = c*own - s*other;
// role1: new = c*own + s*other.
template <int LM, int RM, int RHOL, int RHOR>
__device__ __forceinline__ void ry_p(u64* re, u64* im, int lane, float c, float s)
{
    const bool lp = (__popc(lane & RHOL) & 1) != 0;
    constexpr int flip = RHOR & 1;
    const float s00 = lp ? s : -s;                    // base parity 0, element 0
    const float s01 = (lp ^ (flip != 0)) ? s : -s;    // base parity 0, element 1
    const u64 C  = pk(c, c);
    const u64 S0 = pk(s00, s01);
    const u64 S1 = pk(-s00, -s01);                    // base parity 1 = negated roles

    constexpr int RMH = RM >> 1;   // pack-level xor
    constexpr int SW  = RM & 1;    // intra-pack element swap

    if (RMH == 0) {
#pragma unroll
        for (int k = 0; k < 16; k++) {
            const u64 S = parc((2 * k) & RHOR) ? S1 : S0;
            u64 oR = re[k], oI = im[k];
            if (SW)  { oR = swap64(oR); oI = swap64(oI); }
            if (LM != 0) {
                oR = __shfl_xor_sync(0xffffffffu, oR, LM);
                oI = __shfl_xor_sync(0xffffffffu, oI, LM);
            }
            re[k] = fma2(S, oR, mul2(C, re[k]));
            im[k] = fma2(S, oI, mul2(C, im[k]));
        }
    } else {
        constexpr int PB = RMH & (-RMH);
#pragma unroll
        for (int k0 = 0; k0 < 16; k0++) {
            if ((k0 & PB) == 0) {
                const int k1 = k0 ^ RMH;
                const u64 Sa = parc((2 * k0) & RHOR) ? S1 : S0;
                const u64 Sb = parc((2 * k1) & RHOR) ? S1 : S0;
                u64 v0R = re[k0], v0I = im[k0];
                u64 v1R = re[k1], v1I = im[k1];
                u64 o0R = v1R, o0I = v1I, o1R = v0R, o1I = v0I;
                if (SW) {
                    o0R = swap64(o0R); o0I = swap64(o0I);
                    o1R = swap64(o1R); o1I = swap64(o1I);
                }
                if (LM != 0) {
                    o0R = __shfl_xor_sync(0xffffffffu, o0R, LM);
                    o0I = __shfl_xor_sync(0xffffffffu, o0I, LM);
                    o1R = __shfl_xor_sync(0xffffffffu, o1R, LM);
                    o1I = __shfl_xor_sync(0xffffffffu, o1I, LM);
                }
                re[k0] = fma2(Sa, o0R, mul2(C, v0R));
                im[k0] = fma2(Sa, o0I, mul2(C, v0I));
                re[k1] = fma2(Sb, o1R, mul2(C, v1R));
                im[k1] = fma2(Sb, o1I, mul2(C, v1I));
            }
        }
    }
}

__global__ __launch_bounds__(NTHREADS, 2)
void qsim_reg_kernel(const float* __restrict__ x, float* __restrict__ out, int B)
{
    const int lane = threadIdx.x & 31;
    const int warp = threadIdx.x >> 5;
    const int b = blockIdx.x * WPB + warp;
    if (b >= B) return;

    u64 re[16], im[16];  // re[k] = (amp[2k].re, amp[2k+1].re) packed f32x2

    // ---- Load raw (normalization folded into RY1 gate 0) ----
    const ulonglong2* xb = (const ulonglong2*)(x + (size_t)b * DIMQ + lane * 32);
    u64 ssP = 0ull;
#pragma unroll
    for (int j = 0; j < 8; j++) {
        ulonglong2 v = xb[j];
        re[2 * j + 0] = v.x;
        re[2 * j + 1] = v.y;
        ssP = fma2(v.x, v.x, ssP);
        ssP = fma2(v.y, v.y, ssP);
    }
    float2 ssf = upk(ssP);
    float ss = ssf.x + ssf.y;
#pragma unroll
    for (int o = 16; o > 0; o >>= 1)
        ss += __shfl_xor_sync(0xffffffffu, ss, o);
    const float inv = rsqrtf(ss);

    // ---- D_phi1 on real state: im = sin*v, re = cos*v ----
#pragma unroll
    for (int k = 0; k < 16; k++) {
        const u64 dR = __ldg(&g_d1r[k * 32 + lane]);
        const u64 dI = __ldg(&g_d1i[k * 32 + lane]);
        const u64 v = re[k];
        re[k] = mul2(dR, v);
        im[k] = mul2(dI, v);
    }

    // ---- RY layer 1 (plain bit masks); gate 0 carries the normalization ----
    {
        float2 g;
#define RG(i) g = __ldg(&g_ry[i])
        RG(0); ry_p<16, 0, 16,  0>(re, im, lane, g.x * inv, g.y * inv);
        RG(1); ry_p< 8, 0,  8,  0>(re, im, lane, g.x, g.y);
        RG(2); ry_p< 4, 0,  4,  0>(re, im, lane, g.x, g.y);
        RG(3); ry_p< 2, 0,  2,  0>(re, im, lane, g.x, g.y);
        RG(4); ry_p< 1, 0,  1,  0>(re, im, lane, g.x, g.y);
        RG(5); ry_p< 0,16,  0, 16>(re, im, lane, g.x, g.y);
        RG(6); ry_p< 0, 8,  0,  8>(re, im, lane, g.x, g.y);
        RG(7); ry_p< 0, 4,  0,  4>(re, im, lane, g.x, g.y);
        RG(8); ry_p< 0, 2,  0,  2>(re, im, lane, g.x, g.y);
        RG(9); ry_p< 0, 1,  0,  1>(re, im, lane, g.x, g.y);

        // ---- D_mid = D_omega1 * D_phi2 (complex unit diagonal) ----
#pragma unroll
        for (int k = 0; k < 16; k++) {
            const u64 dR  = __ldg(&g_dmr [k * 32 + lane]);
            const u64 dI  = __ldg(&g_dmi [k * 32 + lane]);
            const u64 dIn = __ldg(&g_dmin[k * 32 + lane]);
            const u64 vR = re[k], vI = im[k];
            re[k] = fma2(dIn, vI, mul2(dR, vR));
            im[k] = fma2(dI,  vR, mul2(dR, vI));
        }

        // ---- RY layer 2 (CNOT-ring-1-absorbed masks/roles; verified round 4) ----
        RG(10); ry_p<24, 0, 15, 31>(re, im, lane, g.x, g.y);
        RG(11); ry_p<12, 0, 24,  0>(re, im, lane, g.x, g.y);
        RG(12); ry_p< 6, 0, 28,  0>(re, im, lane, g.x, g.y);
        RG(13); ry_p< 3, 0, 30,  0>(re, im, lane, g.x, g.y);
        RG(14); ry_p< 1,16, 31,  0>(re, im, lane, g.x, g.y);
        RG(15); ry_p< 0,24, 31, 16>(re, im, lane, g.x, g.y);
        RG(16); ry_p< 0,12, 31, 24>(re, im, lane, g.x, g.y);
        RG(17); ry_p< 0, 6, 31, 28>(re, im, lane, g.x, g.y);
        RG(18); ry_p< 0, 3, 31, 30>(re, im, lane, g.x, g.y);
        RG(19); ry_p<24, 1, 31, 31>(re, im, lane, g.x, g.y);
#undef RG
        // D_omega2: unit diagonal, |amp|^2 invariant -> dropped.
    }

    // ---- probs -> signed sums via 4-stage WHT over pack index ----
    u64 W[16];
#pragma unroll
    for (int k = 0; k < 16; k++)
        W[k] = fma2(re[k], re[k], mul2(im[k], im[k]));
#pragma unroll
    for (int s = 1; s < 16; s <<= 1) {
#pragma unroll
        for (int k = 0; k < 16; k++) {
            if ((k & s) == 0) {
                const u64 a = W[k], c = W[k | s];
                W[k] = add2(a, c);
                W[k | s] = sub2(a, c);
            }
        }
    }
    float av[10];
    {
        float2 w3  = upk(W[3]);
        float2 w9  = upk(W[9]);
        float2 w15 = upk(W[15]);
        float2 w0  = upk(W[0]);
        float2 w8  = upk(W[8]);
        float2 w6  = upk(W[6]);
        float2 w12 = upk(W[12]);
        av[0] = w3.x  + w3.y;    // Z_R=6
        av[1] = w9.x  - w9.y;    // Z_R=19
        av[2] = w15.x - w15.y;   // Z_R=31
        av[3] = w0.x  + w0.y;    // Z_R=0
        av[4] = av[2];           // Z_R=31
        av[5] = w8.x  + w8.y;    // Z_R=16
        av[6] = w3.x  - w3.y;    // Z_R=7
        av[7] = w6.x  + w6.y;    // Z_R=12
        av[8] = w12.x - w12.y;   // Z_R=25
        av[9] = av[1];           // Z_R=19
    }
#define SGNL(i, ZL) if (par((unsigned)(lane & (ZL)))) av[i] = -av[i];
    SGNL(0,  3)
    SGNL(1,  1)
    SGNL(2, 19)
    SGNL(3,  6)
    SGNL(4, 12)
    SGNL(5, 25)
    SGNL(6, 19)
    SGNL(7,  6)
    SGNL(8, 12)
    SGNL(9, 25)
#undef SGNL

    // ---- paired warp reduction (5 u64 lanes-sums instead of 10 floats) ----
    u64 A[5];
#pragma unroll
    for (int j = 0; j < 5; j++) A[j] = pk(av[2 * j], av[2 * j + 1]);
#pragma unroll
    for (int o = 16; o > 0; o >>= 1) {
#pragma unroll
        for (int j = 0; j < 5; j++)
            A[j] = add2(A[j], __shfl_xor_sync(0xffffffffu, A[j], o));
    }
    if (lane < NQ) {
        float2 f = upk(A[lane >> 1]);
        out[(size_t)b * NQ + lane] = (lane & 1) ? f.y : f.x;
    }
}

extern "C" void kernel_launch(void* const* d_in, const int* in_sizes, int n_in,
                              void* d_out, int out_size)
{
    const float* x;
    const float* w;
    int xsize;
    if (in_sizes[0] == NL * NQ * 3) {
        w = (const float*)d_in[0];
        x = (const float*)d_in[1];
        xsize = in_sizes[1];
    } else {
        x = (const float*)d_in[0];
        w = (const float*)d_in[1];
        xsize = in_sizes[0];
    }
    const int B = xsize / DIMQ;
    float* out = (float*)d_out;
    prep_kernel<<<1, DIMQ>>>(w);
    qsim_reg_kernel<<<(B + WPB - 1) / WPB, NTHREADS>>>(x, out, B);
    (void)n_in; (void)out_size;
}